// round 11
// baseline (speedup 1.0000x reference)
#include <cuda_runtime.h>

// Problem constants
#define BB 4
#define TT 2048
#define NE 32
#define NH 8
#define NB 512                      // 4-row blocks per (b,h)
#define NSLICE 64                   // xpart slices per batch (32 rows each)
#define ROWS_B 32                   // kernel B rows per CTA
#define THR_B 256                   // 8 warps: warp = head, lane = row
#define NCTA_B ((BB * TT) / ROWS_B) // 256

// g_xpart[b][s][c*32+e] = sum over slice-s rows with (row%4==c) of x[row][e]
__device__ __align__(16) float g_xpart[BB][NSLICE][128];

__device__ __forceinline__ float clip100(float v) {
    return fminf(fmaxf(v, -100.0f), 100.0f);
}

// -------- Kernel A: partial column sums of x, bucketed by (row % 4) --------
__global__ __launch_bounds__(128) void xpart_kernel(const float* __restrict__ x)
{
    const int b   = blockIdx.x >> 6;
    const int s   = blockIdx.x & 63;
    const int tid = threadIdx.x;

    const float* xs0 = x + ((size_t)b * TT + (size_t)s * 32) * NE;
    float acc = 0.0f;
    #pragma unroll
    for (int j = 0; j < 8; ++j) acc += xs0[j * 128 + tid];
    g_xpart[b][s][tid] = acc;
}

// -------- Kernel B: fused Vbar/G + q, RXTX, softmax, z = bp + P.G^T --------
// 256 threads = 8 warps (w = head) x 32 lanes (l = row).
// Warps 0-3 additionally own Vbar bucket c = w and build G via shuffles.
__global__ __launch_bounds__(THR_B, 2) void rxtx_attn_kernel(
    const float* __restrict__ x,
    const float* __restrict__ Wq, const float* __restrict__ bq,
    const float* __restrict__ Wv, const float* __restrict__ bv,
    const float* __restrict__ Wp, const float* __restrict__ bp,
    float* __restrict__ out)
{
    __shared__ __align__(16) float sWq[NE][NE];   // 128B rows; float4 broadcasts
    __shared__ float sWv[NE][33];                  // per-lane rows, stride 33
    __shared__ float sWp[NE][33];
    __shared__ __align__(16) float sGT[NE][36];   // G transposed; float4 broadcasts
    __shared__ float sbq[NE];
    __shared__ float sbp[NE];
    __shared__ float sbv[NE];
    __shared__ __align__(16) float sX[ROWS_B][36]; // x rows
    __shared__ __align__(16) float sQ[ROWS_B][36]; // q (float4 access)
    __shared__ __align__(16) float sP[ROWS_B][36]; // softmax probs

    const int tid = threadIdx.x;
    const int w   = tid >> 5;           // warp = head
    const int l   = tid & 31;           // lane = row
    const int tg0 = blockIdx.x * ROWS_B;
    const int b   = tg0 >> 11;          // 64 CTAs per batch, aligned

    // ================= Phase 0: stage everything (vectorized) =================
    {
        const int ro = tid >> 3, cg = (tid & 7) * 4;    // 256 float4s cover 32x32
        *(float4*)&sWq[ro][cg] = ((const float4*)Wq)[tid];
        const float4 wv = ((const float4*)Wv)[tid];
        sWv[ro][cg + 0] = wv.x; sWv[ro][cg + 1] = wv.y;
        sWv[ro][cg + 2] = wv.z; sWv[ro][cg + 3] = wv.w;
        const float4 wp = ((const float4*)Wp)[tid];
        sWp[ro][cg + 0] = wp.x; sWp[ro][cg + 1] = wp.y;
        sWp[ro][cg + 2] = wp.z; sWp[ro][cg + 3] = wp.w;
        *(float4*)&sX[ro][cg] = ((const float4*)(x + (size_t)tg0 * NE))[tid];
    }
    if (tid < NE)           sbq[tid]          = bq[tid];
    else if (tid < 2 * NE)  sbp[tid - NE]     = bp[tid - NE];
    else if (tid < 3 * NE)  sbv[tid - 2 * NE] = bv[tid - 2 * NE];

    // Early-issue Vbar bucket reduce (warps 0-3): L2 loads hidden behind
    // the staging barrier and phase-1 compute; consumed after q matvec.
    float xb = 0.0f;
    if (w < 4) {
        const int c = w;
        #pragma unroll 16
        for (int s = 0; s < NSLICE; ++s)               // coalesced 128B/warp
            xb += g_xpart[b][s][c * 32 + l];
    }
    __syncthreads();

    // ========== Phase 1: q matvec (all warps) ==========
    const int o0 = w * 4;
    {
        float xr[NE];
        #pragma unroll
        for (int k = 0; k < 8; ++k) {                   // float4, conflict-free
            const float4 v = *(const float4*)&sX[l][k * 4];
            xr[4*k] = v.x; xr[4*k+1] = v.y; xr[4*k+2] = v.z; xr[4*k+3] = v.w;
        }
        float qv[4];
        #pragma unroll
        for (int i = 0; i < 4; ++i) {
            const int o = o0 + i;                       // warp-uniform
            const float4* wrow = (const float4*)&sWq[o][0];
            float a = sbq[o];
            #pragma unroll
            for (int k = 0; k < 8; ++k) {
                const float4 v = wrow[k];               // broadcast LDS.128
                a += xr[4*k] * v.x + xr[4*k+1] * v.y
                   + xr[4*k+2] * v.z + xr[4*k+3] * v.w;
            }
            qv[i] = clip100(a);
        }
        *(float4*)&sQ[l][o0] = make_float4(qv[0], qv[1], qv[2], qv[3]);
    }

    // ===== Vbar + G build inside warps 0-3 (register/shuffle, no sVb) =====
    if (w < 4) {
        const int c = w;
        xb *= (1.0f / (float)NB);
        // Vb[c][o] with o = lane: shuffle-dot against Wv rows
        float acc = sbv[l];
        #pragma unroll
        for (int e = 0; e < NE; ++e)
            acc += __shfl_sync(0xffffffffu, xb, e) * sWv[l][e];
        // G[h*4+c][o] = sum_d Vb[c][h*4+d] * Wp[o][h*4+d]; store transposed
        #pragma unroll
        for (int h = 0; h < NH; ++h) {
            float gv = 0.0f;
            #pragma unroll
            for (int d = 0; d < 4; ++d)
                gv += __shfl_sync(0xffffffffu, acc, h * 4 + d) * sWp[l][h * 4 + d];
            sGT[l][h * 4 + c] = gv;
        }
    }
    __syncwarp();   // RXTX only needs this warp's sQ columns

    // ================= Phase 2: RXTX + 4-way softmax =================
    {
        const int blk = l & ~3;
        const int rr  = l & 3;
        const float4 q0 = *(const float4*)&sQ[blk + 0][o0];
        const float4 q1 = *(const float4*)&sQ[blk + 1][o0];
        const float4 q2 = *(const float4*)&sQ[blk + 2][o0];
        const float4 q3 = *(const float4*)&sQ[blk + 3][o0];
        const float X1 = q0.x,  X2 = q0.y,  X3 = q0.z,  X4 = q0.w;
        const float X5 = q1.x,  X6 = q1.y,  X7 = q1.z,  X8 = q1.w;
        const float X9 = q2.x,  X10 = q2.y, X11 = q2.z, X12 = q2.w;
        const float X13 = q3.x, X14 = q3.y, X15 = q3.z, X16 = q3.w;

        const float m1  = (-X2 + X3 - X4 + X8) * (X8 + X11);
        const float m2  = (X1 - X5 - X6 + X7) * (X15 + X5);
        const float m3  = (-X2 + X12) * (-X10 + X16 + X12);
        const float m4  = (X9 - X6) * (X13 + X9 - X14);
        const float m5  = (X2 + X11) * (-X6 + X15 - X7);
        const float m6  = (X6 + X11) * (X6 + X7 - X11);
        const float m7  = X11 * (X6 + X7);
        const float m8  = X2 * (-X14 - X10 + X6 - X15 + X7 + X16 + X12);
        const float m9  = X6 * (X13 + X9 - X14 - X10 + X6 + X7 - X11);
        const float m10 = (X2 - X3 + X7 + X11 + X4 - X8) * X11;
        const float m11 = (X5 + X6 - X7) * X5;
        const float m12 = (X2 - X3 + X4) * X8;
        const float m13 = (-X1 + X5 + X6 + X3 - X7 + X11) * X15;
        const float m14 = (-X1 + X5 + X6) * (X13 + X9 + X15);
        const float m15 = (X2 + X4 - X8) * (X11 + X16 + X12);
        const float m16 = (X1 - X8) * (X9 - X16);
        const float m17 = X12 * (X10 - X12);
        const float m18 = X9 * (X13 - X14);
        const float m19 = (-X2 + X3) * (-X15 + X7 + X8);
        const float m20 = (X5 + X9 - X8) * X9;
        const float m21 = X8 * (X9 - X8 + X12);
        const float m22 = (-X6 + X7) * (X5 + X7 - X11);
        const float m23 = X1 * (X13 - X5 + X16);
        const float m24 = (-X1 + X4 + X12) * X16;
        const float m25 = (X9 + X2 + X10) * X14;
        const float m26 = (X6 + X10 + X12) * X10;

        const float z1 = m7 - m11 - m12;
        const float z2 = m1 + m12 + m21;
        const float z3 = m3 + m17 - m24;
        const float z4 = m2 + m11 + m23;
        const float z5 = m5 + m7 + m8;
        const float z6 = m4 - m18 - m20;
        const float z7 = m6 - m7 - m9;
        const float z8 = m17 + m18;

        const float c01 = m2 - m5 - z1 + m13 + m19;
        const float c02 = z2 + z3 + m15 + m16;
        const float c03 = z4 - z3 - z5 - m13;
        const float c11 = m1 + m6 - z1 + m10 + m22;
        const float c12 = z2 - z6 + z7 + m10;
        const float c13 = z4 + z6 + m14 + m16;
        const float c22 = m4 - z7 - z8 + m26;
        const float c23 = m3 + z5 + z8 + m25;

        float a0, a1, a2, a3;
        if      (rr == 0) { a0 = 0.0f; a1 = c01;  a2 = c02;  a3 = c03;  }
        else if (rr == 1) { a0 = c01;  a1 = c11;  a2 = c12;  a3 = c13;  }
        else if (rr == 2) { a0 = c02;  a1 = c12;  a2 = c22;  a3 = c23;  }
        else              { a0 = c03;  a1 = c13;  a2 = c23;  a3 = 0.0f; }

        a0 = clip100(a0) * 0.5f;
        a1 = clip100(a1) * 0.5f;
        a2 = clip100(a2) * 0.5f;
        a3 = clip100(a3) * 0.5f;

        const float mx = fmaxf(fmaxf(a0, a1), fmaxf(a2, a3));
        const float e0 = __expf(a0 - mx);
        const float e1 = __expf(a1 - mx);
        const float e2 = __expf(a2 - mx);
        const float e3 = __expf(a3 - mx);
        const float inv = 1.0f / (e0 + e1 + e2 + e3);

        *(float4*)&sP[l][o0] = make_float4(e0 * inv, e1 * inv, e2 * inv, e3 * inv);
    }
    __syncthreads();   // single barrier: covers sP (all warps) and sGT (warps 0-3)

    // ========== Phase 3: z = bp + P . G^T + direct store ==========
    {
        float pr[NE];
        #pragma unroll
        for (int k = 0; k < 8; ++k) {
            const float4 v = *(const float4*)&sP[l][k * 4];
            pr[4*k] = v.x; pr[4*k+1] = v.y; pr[4*k+2] = v.z; pr[4*k+3] = v.w;
        }
        float zv[4];
        #pragma unroll
        for (int i = 0; i < 4; ++i) {
            const int o = o0 + i;                        // warp-uniform
            const float4* grow = (const float4*)&sGT[o][0];
            float a = sbp[o];
            #pragma unroll
            for (int k = 0; k < 8; ++k) {
                const float4 v = grow[k];                // broadcast LDS.128
                a += pr[4*k] * v.x + pr[4*k+1] * v.y
                   + pr[4*k+2] * v.z + pr[4*k+3] * v.w;
            }
            zv[i] = a;
        }
        // direct 16B store: row tg0+l, cols [o0, o0+4)
        *(float4*)(out + ((size_t)(tg0 + l)) * NE + o0) =
            make_float4(zv[0], zv[1], zv[2], zv[3]);
    }
}

extern "C" void kernel_launch(void* const* d_in, const int* in_sizes, int n_in,
                              void* d_out, int out_size)
{
    // metadata order: x, Wq, bq, Wk, bk, Wv, bv, Wp, bp   (Wk/bk dead)
    const float* x  = (const float*)d_in[0];
    const float* Wq = (const float*)d_in[1];
    const float* bq = (const float*)d_in[2];
    const float* Wv = (const float*)d_in[5];
    const float* bv = (const float*)d_in[6];
    const float* Wp = (const float*)d_in[7];
    const float* bp = (const float*)d_in[8];
    float* out = (float*)d_out;

    xpart_kernel<<<BB * NSLICE, 128>>>(x);
    rxtx_attn_kernel<<<NCTA_B, THR_B>>>(x, Wq, bq, Wv, bv, Wp, bp, out);
}

// round 12
// speedup vs baseline: 1.1821x; 1.1821x over previous
#include <cuda_runtime.h>

// Problem constants
#define BB 4
#define TT 2048
#define NE 32
#define NH 8
#define NB 512                      // 4-row blocks per (b,h)
#define NSLICE 64                   // xpart slices per batch (32 rows each)
#define ROWS_B 32                   // kernel B rows per CTA
#define THR_B 256                   // 8 warps: warp = head, lane = row
#define NCTA_B ((BB * TT) / ROWS_B) // 256

// g_xpart[b][s][c*32+e] = sum over slice-s rows with (row%4==c) of x[row][e]
__device__ __align__(16) float g_xpart[BB][NSLICE][128];

__device__ __forceinline__ float clip100(float v) {
    return fminf(fmaxf(v, -100.0f), 100.0f);
}

// -------- Kernel A: partial column sums of x, bucketed by (row % 4) --------
__global__ __launch_bounds__(128) void xpart_kernel(const float* __restrict__ x)
{
    const int b   = blockIdx.x >> 6;
    const int s   = blockIdx.x & 63;
    const int tid = threadIdx.x;

    const float* xs0 = x + ((size_t)b * TT + (size_t)s * 32) * NE;
    float acc = 0.0f;
    #pragma unroll
    for (int j = 0; j < 8; ++j) acc += xs0[j * 128 + tid];
    g_xpart[b][s][tid] = acc;
}

// -------- Kernel B: fused Vbar/G + q, RXTX, softmax, z = bp + P.G^T --------
// 256 threads = 8 warps (w = head) x 32 lanes (l = row).
// Warps 0-3 also own Vbar bucket c = w; G built in-warp via shuffles.
__global__ __launch_bounds__(THR_B, 2) void rxtx_attn_kernel(
    const float* __restrict__ x,
    const float* __restrict__ Wq, const float* __restrict__ bq,
    const float* __restrict__ Wv, const float* __restrict__ bv,
    const float* __restrict__ Wp, const float* __restrict__ bp,
    float* __restrict__ out)
{
    __shared__ __align__(16) float sWq[NE][NE];   // 128B rows; float4 broadcasts
    __shared__ float sWv[NE][33];                  // per-lane rows, stride 33
    __shared__ float sWp[NE][33];
    __shared__ __align__(16) float sGT[NE][36];   // G transposed; float4 broadcasts
    __shared__ float sbq[NE];
    __shared__ float sbp[NE];
    __shared__ __align__(16) float sXh8[8][128];  // xpart partials per slice-group
    __shared__ __align__(16) float sX[ROWS_B][36]; // x rows
    __shared__ __align__(16) float sQ[ROWS_B][36]; // q (float4 access)
    __shared__ __align__(16) float sP[ROWS_B][36]; // softmax probs

    const int tid = threadIdx.x;
    const int w   = tid >> 5;           // warp = head
    const int l   = tid & 31;           // lane = row
    const int tg0 = blockIdx.x * ROWS_B;
    const int b   = tg0 >> 11;          // 64 CTAs per batch, aligned

    // ================= Phase 0: stage everything (vectorized) =================
    {
        const int ro = tid >> 3, cg = (tid & 7) * 4;    // 256 float4s cover 32x32
        *(float4*)&sWq[ro][cg] = ((const float4*)Wq)[tid];
        const float4 wv = ((const float4*)Wv)[tid];
        sWv[ro][cg + 0] = wv.x; sWv[ro][cg + 1] = wv.y;
        sWv[ro][cg + 2] = wv.z; sWv[ro][cg + 3] = wv.w;
        const float4 wp = ((const float4*)Wp)[tid];
        sWp[ro][cg + 0] = wp.x; sWp[ro][cg + 1] = wp.y;
        sWp[ro][cg + 2] = wp.z; sWp[ro][cg + 3] = wp.w;
        *(float4*)&sX[ro][cg] = ((const float4*)(x + (size_t)tg0 * NE))[tid];
    }
    if (tid < NE)          sbq[tid]      = bq[tid];
    else if (tid < 2 * NE) sbp[tid - NE] = bp[tid - NE];

    // xpart partial reduce: warp w sums its 8 slices, float4 per lane
    // (independent loads across warps -> high MLP; proven in R5)
    {
        const int fb = l * 4;
        float4 ps = make_float4(0.f, 0.f, 0.f, 0.f);
        #pragma unroll
        for (int s = 0; s < 8; ++s) {
            const float4 v = *(const float4*)&g_xpart[b][w * 8 + s][fb];
            ps.x += v.x; ps.y += v.y; ps.z += v.z; ps.w += v.w;
        }
        *(float4*)&sXh8[w][fb] = ps;
    }
    __syncthreads();

    // ========== Phase 1: q matvec (all warps) + Vbar/G (warps 0-3) ==========
    const int o0 = w * 4;
    {
        float xr[NE];
        #pragma unroll
        for (int k = 0; k < 8; ++k) {                   // float4, conflict-free
            const float4 v = *(const float4*)&sX[l][k * 4];
            xr[4*k] = v.x; xr[4*k+1] = v.y; xr[4*k+2] = v.z; xr[4*k+3] = v.w;
        }
        float qv[4];
        #pragma unroll
        for (int i = 0; i < 4; ++i) {
            const int o = o0 + i;                       // warp-uniform
            const float4* wrow = (const float4*)&sWq[o][0];
            float a = sbq[o];
            #pragma unroll
            for (int k = 0; k < 8; ++k) {
                const float4 v = wrow[k];               // broadcast LDS.128
                a += xr[4*k] * v.x + xr[4*k+1] * v.y
                   + xr[4*k+2] * v.z + xr[4*k+3] * v.w;
            }
            qv[i] = clip100(a);
        }
        *(float4*)&sQ[l][o0] = make_float4(qv[0], qv[1], qv[2], qv[3]);
    }
    if (w < 4) {                        // Vbar bucket c = w, lane = e/o
        const int c = w;
        float xb = 0.0f;
        #pragma unroll
        for (int sg = 0; sg < 8; ++sg) xb += sXh8[sg][c * 32 + l];
        xb *= (1.0f / (float)NB);
        // Vb[c][o] with o = lane: shuffle-dot against Wv rows
        float acc = bv[l];
        #pragma unroll
        for (int e = 0; e < NE; ++e)
            acc += __shfl_sync(0xffffffffu, xb, e) * sWv[l][e];
        // G[h*4+c][o] = sum_d Vb[c][h*4+d] * Wp[o][h*4+d]; store transposed,
        // column h*4+c owned by this warp -> no cross-warp dependency.
        #pragma unroll
        for (int h = 0; h < NH; ++h) {
            float gv = 0.0f;
            #pragma unroll
            for (int d = 0; d < 4; ++d)
                gv += __shfl_sync(0xffffffffu, acc, h * 4 + d) * sWp[l][h * 4 + d];
            sGT[l][h * 4 + c] = gv;
        }
    }
    __syncwarp();   // RXTX only needs this warp's sQ columns

    // ================= Phase 2: RXTX + 4-way softmax =================
    {
        const int blk = l & ~3;
        const int rr  = l & 3;
        const float4 q0 = *(const float4*)&sQ[blk + 0][o0];
        const float4 q1 = *(const float4*)&sQ[blk + 1][o0];
        const float4 q2 = *(const float4*)&sQ[blk + 2][o0];
        const float4 q3 = *(const float4*)&sQ[blk + 3][o0];
        const float X1 = q0.x,  X2 = q0.y,  X3 = q0.z,  X4 = q0.w;
        const float X5 = q1.x,  X6 = q1.y,  X7 = q1.z,  X8 = q1.w;
        const float X9 = q2.x,  X10 = q2.y, X11 = q2.z, X12 = q2.w;
        const float X13 = q3.x, X14 = q3.y, X15 = q3.z, X16 = q3.w;

        const float m1  = (-X2 + X3 - X4 + X8) * (X8 + X11);
        const float m2  = (X1 - X5 - X6 + X7) * (X15 + X5);
        const float m3  = (-X2 + X12) * (-X10 + X16 + X12);
        const float m4  = (X9 - X6) * (X13 + X9 - X14);
        const float m5  = (X2 + X11) * (-X6 + X15 - X7);
        const float m6  = (X6 + X11) * (X6 + X7 - X11);
        const float m7  = X11 * (X6 + X7);
        const float m8  = X2 * (-X14 - X10 + X6 - X15 + X7 + X16 + X12);
        const float m9  = X6 * (X13 + X9 - X14 - X10 + X6 + X7 - X11);
        const float m10 = (X2 - X3 + X7 + X11 + X4 - X8) * X11;
        const float m11 = (X5 + X6 - X7) * X5;
        const float m12 = (X2 - X3 + X4) * X8;
        const float m13 = (-X1 + X5 + X6 + X3 - X7 + X11) * X15;
        const float m14 = (-X1 + X5 + X6) * (X13 + X9 + X15);
        const float m15 = (X2 + X4 - X8) * (X11 + X16 + X12);
        const float m16 = (X1 - X8) * (X9 - X16);
        const float m17 = X12 * (X10 - X12);
        const float m18 = X9 * (X13 - X14);
        const float m19 = (-X2 + X3) * (-X15 + X7 + X8);
        const float m20 = (X5 + X9 - X8) * X9;
        const float m21 = X8 * (X9 - X8 + X12);
        const float m22 = (-X6 + X7) * (X5 + X7 - X11);
        const float m23 = X1 * (X13 - X5 + X16);
        const float m24 = (-X1 + X4 + X12) * X16;
        const float m25 = (X9 + X2 + X10) * X14;
        const float m26 = (X6 + X10 + X12) * X10;

        const float z1 = m7 - m11 - m12;
        const float z2 = m1 + m12 + m21;
        const float z3 = m3 + m17 - m24;
        const float z4 = m2 + m11 + m23;
        const float z5 = m5 + m7 + m8;
        const float z6 = m4 - m18 - m20;
        const float z7 = m6 - m7 - m9;
        const float z8 = m17 + m18;

        const float c01 = m2 - m5 - z1 + m13 + m19;
        const float c02 = z2 + z3 + m15 + m16;
        const float c03 = z4 - z3 - z5 - m13;
        const float c11 = m1 + m6 - z1 + m10 + m22;
        const float c12 = z2 - z6 + z7 + m10;
        const float c13 = z4 + z6 + m14 + m16;
        const float c22 = m4 - z7 - z8 + m26;
        const float c23 = m3 + z5 + z8 + m25;

        float a0, a1, a2, a3;
        if      (rr == 0) { a0 = 0.0f; a1 = c01;  a2 = c02;  a3 = c03;  }
        else if (rr == 1) { a0 = c01;  a1 = c11;  a2 = c12;  a3 = c13;  }
        else if (rr == 2) { a0 = c02;  a1 = c12;  a2 = c22;  a3 = c23;  }
        else              { a0 = c03;  a1 = c13;  a2 = c23;  a3 = 0.0f; }

        a0 = clip100(a0) * 0.5f;
        a1 = clip100(a1) * 0.5f;
        a2 = clip100(a2) * 0.5f;
        a3 = clip100(a3) * 0.5f;

        const float mx = fmaxf(fmaxf(a0, a1), fmaxf(a2, a3));
        const float e0 = __expf(a0 - mx);
        const float e1 = __expf(a1 - mx);
        const float e2 = __expf(a2 - mx);
        const float e3 = __expf(a3 - mx);
        const float inv = 1.0f / (e0 + e1 + e2 + e3);

        *(float4*)&sP[l][o0] = make_float4(e0 * inv, e1 * inv, e2 * inv, e3 * inv);
    }
    __syncthreads();   // single barrier: covers sP (all warps) and sGT (warps 0-3)

    // ========== Phase 3: z = bp + P . G^T + direct store ==========
    {
        float pr[NE];
        #pragma unroll
        for (int k = 0; k < 8; ++k) {
            const float4 v = *(const float4*)&sP[l][k * 4];
            pr[4*k] = v.x; pr[4*k+1] = v.y; pr[4*k+2] = v.z; pr[4*k+3] = v.w;
        }
        float zv[4];
        #pragma unroll
        for (int i = 0; i < 4; ++i) {
            const int o = o0 + i;                        // warp-uniform
            const float4* grow = (const float4*)&sGT[o][0];
            float a = sbp[o];
            #pragma unroll
            for (int k = 0; k < 8; ++k) {
                const float4 v = grow[k];                // broadcast LDS.128
                a += pr[4*k] * v.x + pr[4*k+1] * v.y
                   + pr[4*k+2] * v.z + pr[4*k+3] * v.w;
            }
            zv[i] = a;
        }
        // direct 16B store: row tg0+l, cols [o0, o0+4)
        *(float4*)(out + ((size_t)(tg0 + l)) * NE + o0) =
            make_float4(zv[0], zv[1], zv[2], zv[3]);
    }
}

extern "C" void kernel_launch(void* const* d_in, const int* in_sizes, int n_in,
                              void* d_out, int out_size)
{
    // metadata order: x, Wq, bq, Wk, bk, Wv, bv, Wp, bp   (Wk/bk dead)
    const float* x  = (const float*)d_in[0];
    const float* Wq = (const float*)d_in[1];
    const float* bq = (const float*)d_in[2];
    const float* Wv = (const float*)d_in[5];
    const float* bv = (const float*)d_in[6];
    const float* Wp = (const float*)d_in[7];
    const float* bp = (const float*)d_in[8];
    float* out = (float*)d_out;

    xpart_kernel<<<BB * NSLICE, 128>>>(x);
    rxtx_attn_kernel<<<NCTA_B, THR_B>>>(x, Wq, bq, Wv, bv, Wp, bp, out);
}